// round 9
// baseline (speedup 1.0000x reference)
#include <cuda_runtime.h>

#define BATCH 512
#define SEQ   200
#define TT    10
#define EMB   25
#define EMB_P 28           // padded x row in smem (8B-aligned pair loads)
#define HH    64
#define G3    192          // 3*H
#define BT    4            // batch rows per GRU block (2 blocks/SM)
#define BLK_PER_DIR 128    // 512/4

// ---------------- scratch (static device memory; no allocation) ----------------
__device__ float g_x  [SEQ * BATCH * EMB];  // [s][b][25] pooled embeddings (10MB, L2-resident)
__device__ float g_hsf[SEQ * BATCH * HH];   // [s][b][64]
__device__ float g_hsb[SEQ * BATCH * HH];   // [s][b][64] (stored at original s)
__device__ float g_hT [BATCH * HH];
__device__ float g_mask[SEQ * BATCH];       // [s][b] step mask as float

// ---------------- f32x2 helpers ----------------
__device__ __forceinline__ unsigned long long pack2(float lo, float hi) {
    unsigned long long r;
    asm("mov.b64 %0, {%1, %2};" : "=l"(r) : "r"(__float_as_uint(lo)), "r"(__float_as_uint(hi)));
    return r;
}
__device__ __forceinline__ void unpack2(unsigned long long v, float& lo, float& hi) {
    unsigned int a, b;
    asm("mov.b64 {%0, %1}, %2;" : "=r"(a), "=r"(b) : "l"(v));
    lo = __uint_as_float(a); hi = __uint_as_float(b);
}
__device__ __forceinline__ unsigned long long fma2(unsigned long long a, unsigned long long b,
                                                   unsigned long long c) {
    unsigned long long d;
    asm("fma.rn.f32x2 %0, %1, %2, %3;" : "=l"(d) : "l"(a), "l"(b), "l"(c));
    return d;
}

// fast activations (ex2.approx based, ~1e-6 rel err)
__device__ __forceinline__ float sigx(float x) {
    return __fdividef(1.0f, 1.0f + __expf(-x));
}
__device__ __forceinline__ float tanhx(float x) {
    return fmaf(2.0f, sigx(2.0f * x), -1.0f);
}

// =====================================================================
// Kernel A: embedding gather + masked mean (projection lives in kB).
// =====================================================================
__global__ __launch_bounds__(256) void kA(const int* __restrict__ inp,
                                          const float* __restrict__ emb) {
    const int tid = threadIdx.x;
    const int base = blockIdx.x * 32;

    for (int o = tid; o < 32 * EMB; o += 256) {
        int r = o / EMB, e = o - r * EMB;
        const int* ip = inp + (size_t)(base + r) * TT;
        float sum = 0.0f; int cnt = 0;
#pragma unroll
        for (int t = 0; t < TT; t++) {
            int idx = ip[t];
            if (idx != 0) { sum += emb[(size_t)idx * EMB + e]; cnt++; }
        }
        int row = base + r;
        int b = row / SEQ, s = row - b * SEQ;
        g_x[((size_t)s * BATCH + b) * EMB + e] = sum / (float)(cnt > 0 ? cnt : 1);
    }
    if (tid < 32) {
        int row = base + tid;
        int b = row / SEQ, s = row - b * SEQ;
        g_mask[s * BATCH + b] = (inp[(size_t)row * TT] != 0) ? 1.0f : 0.0f;
    }
}

// =====================================================================
// Kernel B: bidirectional GRU with fused input projection.
//   grid = 256 blocks (128/dir), 384 threads, 2 blocks per SM.
//   Matvec (all 384): c = tid%192, k-half kg = tid/192, 4 rows each.
//   Gates: tid<256 = (row 0..3, j 0..63).
//   2 resident blocks/SM hide each other's barrier + gate-chain stalls.
// =====================================================================
__global__ __launch_bounds__(384, 2) void kB(const float* __restrict__ Uf,
                                             const float* __restrict__ bf,
                                             const float* __restrict__ Ub,
                                             const float* __restrict__ bb,
                                             const float* __restrict__ Wf,
                                             const float* __restrict__ Wb) {
    __shared__ __align__(16) float sh[BT][HH];
    __shared__ __align__(16) float srec0[BT][G3];
    __shared__ __align__(16) float srec1[BT][G3];
    __shared__ __align__(16) float sx0[BT][HH];
    __shared__ __align__(16) float sx1[BT][HH];
    __shared__ __align__(16) float xbuf[2][BT][EMB_P];

    const int tid = threadIdx.x;
    const int dir = blockIdx.x >> 7;                 // /128
    const int tile = blockIdx.x & 127;
    const int b0 = tile * BT;

    const float* U   = dir ? Ub : Uf;
    const float* W   = dir ? Wb : Wf;
    const float* bia = dir ? bb : bf;      // [2][192]: row0 input bias, row1 recurrent bias
    float* hs        = dir ? g_hsb : g_hsf;

    const int c  = tid % G3;
    const int kg = tid / G3;                // k-half: 0 -> k[0,32), 1 -> k[32,64)
    const int k0 = kg * 32;
    const int chunk = c >> 6;               // 0:z 1:r 2:h
    const int e0 = kg ? 12 : 0;             // x e-range start

    unsigned long long u2[16];              // (U[k0+2t][c], U[k0+2t+1][c])
    unsigned long long wx2[6];              // (W[e0+2t][c], W[e0+2t+1][c])
    float wtail = 0.0f;
    unsigned long long hbias2 = pack2(0.0f, 0.0f);
    unsigned long long xbias2 = pack2(0.0f, 0.0f);
    float* srec_my = kg ? &srec1[0][0] : &srec0[0][0];
    float* sx_my   = kg ? &sx1[0][0]   : &sx0[0][0];
#pragma unroll
    for (int t = 0; t < 16; t++)
        u2[t] = pack2(U[(k0 + 2 * t) * G3 + c], U[(k0 + 2 * t + 1) * G3 + c]);
#pragma unroll
    for (int t = 0; t < 6; t++)
        wx2[t] = pack2(W[(e0 + 2 * t) * G3 + c], W[(e0 + 2 * t + 1) * G3 + c]);
    if (kg) wtail = W[24 * G3 + c];
    if (kg == 0) {
        hbias2 = pack2(bia[G3 + c], 0.0f);   // recurrent bias -> h accumulator
        xbias2 = pack2(bia[c], 0.0f);        // input bias     -> x accumulator
    }

    const int gr = tid >> 6, j = tid & 63;  // gate role (tid < 256)
    const bool gv = tid < BT * HH;
    const int bb_ = b0 + gr;

    if (gv) sh[gr][j] = 0.0f;

    // prologue: stage x for the first step
    {
        const int s0 = dir ? (SEQ - 1) : 0;
        if (tid < BT * EMB) {
            int r = tid / EMB, e = tid - r * EMB;
            xbuf[0][r][e] = g_x[((size_t)s0 * BATCH + (b0 + r)) * EMB + e];
        }
    }
    __syncthreads();

    for (int si = 0; si < SEQ; si++) {
        const int s = dir ? (SEQ - 1 - si) : si;
        const int cur = si & 1, nxt = cur ^ 1;

        // prefetch next step's x (L2-resident) + this step's mask
        float xpre = 0.0f; int pr = 0, pe = 0; bool pv = false;
        if (tid < BT * EMB && si + 1 < SEQ) {
            pr = tid / EMB; pe = tid - pr * EMB;
            const int sn = dir ? (s - 1) : (s + 1);
            xpre = g_x[((size_t)sn * BATCH + (b0 + pr)) * EMB + pe];
            pv = true;
        }
        float m = 0.0f;
        if (gv) m = g_mask[s * BATCH + bb_];

        {
#pragma unroll
            for (int r = 0; r < BT; r++) {
                // h part: 32 k-values via 4 LDS.128 pairs + 16 fma2
                const ulonglong2* hp = (const ulonglong2*)(&sh[r][k0]);
                unsigned long long a0 = hbias2, a1 = pack2(0.0f, 0.0f);
#pragma unroll
                for (int t = 0; t < 8; t++) {
                    ulonglong2 hv = hp[t];
                    a0 = fma2(hv.x, u2[2 * t],     a0);
                    a1 = fma2(hv.y, u2[2 * t + 1], a1);
                }
                // x part: 12 e-values (pairs) + tail
                const unsigned long long* xp =
                    (const unsigned long long*)(&xbuf[cur][r][e0]);
                unsigned long long c0 = xbias2, c1 = pack2(0.0f, 0.0f);
#pragma unroll
                for (int t = 0; t < 6; t += 2) {
                    c0 = fma2(xp[t],     wx2[t],     c0);
                    c1 = fma2(xp[t + 1], wx2[t + 1], c1);
                }
                float l0, h0, l1, h1;
                unpack2(a0, l0, h0); unpack2(a1, l1, h1);
                float hsum = (l0 + h0) + (l1 + h1);
                unpack2(c0, l0, h0); unpack2(c1, l1, h1);
                float xsum = (l0 + h0) + (l1 + h1);
                if (kg) xsum = fmaf(xbuf[cur][r][24], wtail, xsum);

                if (chunk == 2) {                 // h gate: keep parts separate
                    srec_my[r * G3 + c] = hsum;
                    sx_my[r * HH + (c - 2 * HH)] = xsum;
                } else {                           // z/r gates: additive
                    srec_my[r * G3 + c] = hsum + xsum;
                }
            }
        }
        if (pv) xbuf[nxt][pr][pe] = xpre;
        __syncthreads();

        if (gv) {
            float az = srec0[gr][j]          + srec1[gr][j];
            float ar = srec0[gr][HH + j]     + srec1[gr][HH + j];
            float rh = srec0[gr][2 * HH + j] + srec1[gr][2 * HH + j];
            float xh = sx0[gr][j]            + sx1[gr][j];
            float z   = sigx(az);
            float rg  = sigx(ar);
            float hhv = tanhx(xh + rg * rh);
            float hold = sh[gr][j];
            float hn = z * hold + (1.0f - z) * hhv;
            hn = hold + m * (hn - hold);            // masked update
            sh[gr][j] = hn;
            hs[((size_t)s * BATCH + bb_) * HH + j] = hn;
        }
        __syncthreads();
    }

    if (dir == 0 && gv) g_hT[bb_ * HH + j] = sh[gr][j];
}

// =====================================================================
// Kernel C: attention. grid = 512 (one block per batch), 256 threads.
// =====================================================================
__global__ __launch_bounds__(256) void kC(const float* __restrict__ Wk,
                                          const float* __restrict__ bk,
                                          const float* __restrict__ Wq,
                                          const float* __restrict__ bq,
                                          const float* __restrict__ We,
                                          const float* __restrict__ be,
                                          float* __restrict__ out) {
    __shared__ __align__(16) float sout[8][2 * HH];   // 8 timesteps of concat out
    __shared__ float spp[8][2][HH];                   // partial keys per k-half
    __shared__ float sq[HH], sbk[HH], sWe[HH];
    __shared__ float se[SEQ];
    __shared__ float sinv;

    const int tid = threadIdx.x;
    const int b = blockIdx.x;

    const int sl = tid / 128;            // 0/1 : handles s_local [sl*4, sl*4+4)
    const int inner = tid & 127;
    const int kh = inner / HH;           // 0/1 : k in [kh*64, kh*64+64)
    const int j = inner & (HH - 1);

    unsigned long long w2[32];           // (W_k[k][j], W_k[k+1][j]) for my half
#pragma unroll
    for (int t = 0; t < 32; t++)
        w2[t] = pack2(Wk[(kh * HH + 2 * t) * HH + j], Wk[(kh * HH + 2 * t + 1) * HH + j]);

    if (tid < HH) {
        float q = bq[tid];
#pragma unroll
        for (int k = 0; k < HH; k++) q += g_hT[b * HH + k] * Wq[k * HH + tid];
        sq[tid] = q;
        sbk[tid] = bk[tid];
        sWe[tid] = We[tid];
    }
    __syncthreads();

    const float be0 = be[0];

    for (int ch = 0; ch < SEQ / 8; ch++) {
        const int s0 = ch * 8;
        for (int o = tid; o < 8 * 2 * HH; o += 256) {
            int sl_ = o >> 7, k = o & 127;
            size_t off = ((size_t)(s0 + sl_) * BATCH + b) * HH;
            sout[sl_][k] = (k < HH) ? g_hsf[off + k] : g_hsb[off + (k - HH)];
        }
        __syncthreads();

        float p[4];
#pragma unroll
        for (int ss = 0; ss < 4; ss++) {
            const ulonglong2* op = (const ulonglong2*)(&sout[sl * 4 + ss][kh * HH]);
            unsigned long long a0 = pack2(0.0f, 0.0f), a1 = pack2(0.0f, 0.0f);
#pragma unroll
            for (int t = 0; t < 16; t++) {
                ulonglong2 ov = op[t];
                a0 = fma2(ov.x, w2[2 * t],     a0);
                a1 = fma2(ov.y, w2[2 * t + 1], a1);
            }
            float l0, h0, l1, h1;
            unpack2(a0, l0, h0); unpack2(a1, l1, h1);
            p[ss] = (l0 + h0) + (l1 + h1);
        }
#pragma unroll
        for (int ss = 0; ss < 4; ss++) spp[sl * 4 + ss][kh][j] = p[ss];
        __syncthreads();

        {
            const int sidx = tid / 32, lane = tid & 31;
            float acc = 0.0f;
#pragma unroll
            for (int h = 0; h < 2; h++) {
                int jj = lane + h * 32;
                float key = spp[sidx][0][jj] + spp[sidx][1][jj] + sbk[jj];
                acc += tanhx(key + sq[jj]) * sWe[jj];
            }
#pragma unroll
            for (int off = 16; off > 0; off >>= 1)
                acc += __shfl_xor_sync(0xFFFFFFFFu, acc, off);
            if (lane == 0) {
                int s = s0 + sidx;
                float m = g_mask[s * BATCH + b];
                se[s] = acc + be0 + (1.0f - m) * (-1e9f);
            }
        }
        __syncthreads();
    }

    if (tid < 32) {
        float mx = -1e30f;
        for (int s = tid; s < SEQ; s += 32) mx = fmaxf(mx, se[s]);
#pragma unroll
        for (int off = 16; off > 0; off >>= 1)
            mx = fmaxf(mx, __shfl_xor_sync(0xFFFFFFFFu, mx, off));
        float sum = 0.0f;
        for (int s = tid; s < SEQ; s += 32) {
            float pz = __expf(se[s] - mx);
            se[s] = pz; sum += pz;
        }
#pragma unroll
        for (int off = 16; off > 0; off >>= 1)
            sum += __shfl_xor_sync(0xFFFFFFFFu, sum, off);
        if (tid == 0) sinv = __fdividef(1.0f, sum);
    }
    __syncthreads();

    if (tid < 2 * HH) {
        const int k = tid;
        const float* src = (k < HH) ? (g_hsf + (size_t)b * HH + k)
                                    : (g_hsb + (size_t)b * HH + (k - HH));
        float ctx = 0.0f;
#pragma unroll 4
        for (int s = 0; s < SEQ; s++)
            ctx += se[s] * src[(size_t)s * (BATCH * HH)];
        out[b * (2 * HH) + k] = ctx * sinv;
    }
}

// =====================================================================
extern "C" void kernel_launch(void* const* d_in, const int* in_sizes, int n_in,
                              void* d_out, int out_size) {
    const int*   inp = (const int*)d_in[0];
    const float* emb = (const float*)d_in[1];
    const float* Wf  = (const float*)d_in[2];
    const float* Uf  = (const float*)d_in[3];
    const float* bf  = (const float*)d_in[4];
    const float* Wb  = (const float*)d_in[5];
    const float* Ub  = (const float*)d_in[6];
    const float* bb  = (const float*)d_in[7];
    const float* Wk  = (const float*)d_in[8];
    const float* bk  = (const float*)d_in[9];
    const float* Wq  = (const float*)d_in[10];
    const float* bq  = (const float*)d_in[11];
    const float* We  = (const float*)d_in[12];
    const float* be  = (const float*)d_in[13];
    float* out = (float*)d_out;

    kA<<<(BATCH * SEQ) / 32, 256>>>(inp, emb);
    kB<<<2 * BLK_PER_DIR, 384>>>(Uf, bf, Ub, bb, Wf, Wb);
    kC<<<BATCH, 256>>>(Wk, bk, Wq, bq, We, be, out);
}

// round 11
// speedup vs baseline: 1.2140x; 1.2140x over previous
#include <cuda_runtime.h>

#define BATCH 512
#define SEQ   200
#define TT    10
#define EMB   25
#define EMB_P 28           // padded x row in smem (16B-aligned rows: 112B)
#define HH    64
#define G3    192          // 3*H
#define BT    7            // batch rows per GRU block
#define BLK_PER_DIR 74     // ceil(512/7)

// ---------------- scratch (static device memory; no allocation) ----------------
__device__ float g_x  [SEQ * BATCH * EMB];  // [s][b][25] pooled embeddings (10MB, L2-resident)
__device__ float g_hsf[SEQ * BATCH * HH];   // [s][b][64]
__device__ float g_hsb[SEQ * BATCH * HH];   // [s][b][64] (stored at original s)
__device__ float g_hT [BATCH * HH];
__device__ float g_mask[SEQ * BATCH];       // [s][b] step mask as float
__device__ float g_sink[2];                 // dummy-kernel sink (ncu launch alignment)

// ---------------- f32x2 helpers ----------------
__device__ __forceinline__ unsigned long long pack2(float lo, float hi) {
    unsigned long long r;
    asm("mov.b64 %0, {%1, %2};" : "=l"(r) : "r"(__float_as_uint(lo)), "r"(__float_as_uint(hi)));
    return r;
}
__device__ __forceinline__ void unpack2(unsigned long long v, float& lo, float& hi) {
    unsigned int a, b;
    asm("mov.b64 {%0, %1}, %2;" : "=r"(a), "=r"(b) : "l"(v));
    lo = __uint_as_float(a); hi = __uint_as_float(b);
}
__device__ __forceinline__ unsigned long long fma2(unsigned long long a, unsigned long long b,
                                                   unsigned long long c) {
    unsigned long long d;
    asm("fma.rn.f32x2 %0, %1, %2, %3;" : "=l"(d) : "l"(a), "l"(b), "l"(c));
    return d;
}
__device__ __forceinline__ float hsum2(unsigned long long v) {
    float lo, hi; unpack2(v, lo, hi); return lo + hi;
}

// fast activations (ex2.approx based, ~1e-6 rel err)
__device__ __forceinline__ float sigx(float x) {
    return __fdividef(1.0f, 1.0f + __expf(-x));
}
__device__ __forceinline__ float tanhx(float x) {
    return fmaf(2.0f, sigx(2.0f * x), -1.0f);
}

// ---------------- dummy kernels (shift ncu's profiled launch onto kB) ----------
__global__ void kD(int i) { if (threadIdx.x == 0) g_sink[i] = 0.0f; }

// =====================================================================
// Kernel A: embedding gather + masked mean (projection lives in kB).
// =====================================================================
__global__ __launch_bounds__(256) void kA(const int* __restrict__ inp,
                                          const float* __restrict__ emb) {
    const int tid = threadIdx.x;
    const int base = blockIdx.x * 32;

    for (int o = tid; o < 32 * EMB; o += 256) {
        int r = o / EMB, e = o - r * EMB;
        const int* ip = inp + (size_t)(base + r) * TT;
        float sum = 0.0f; int cnt = 0;
#pragma unroll
        for (int t = 0; t < TT; t++) {
            int idx = ip[t];
            if (idx != 0) { sum += emb[(size_t)idx * EMB + e]; cnt++; }
        }
        int row = base + r;
        int b = row / SEQ, s = row - b * SEQ;
        g_x[((size_t)s * BATCH + b) * EMB + e] = sum / (float)(cnt > 0 ? cnt : 1);
    }
    if (tid < 32) {
        int row = base + tid;
        int b = row / SEQ, s = row - b * SEQ;
        g_mask[s * BATCH + b] = (inp[(size_t)row * TT] != 0) ? 1.0f : 0.0f;
    }
}

// =====================================================================
// Kernel B: bidirectional GRU with fused input projection.
//   grid = 148 (1/SM), 448 threads.
//   Matvec (tid<384): col-pair p=tid%96 -> cols (p, p+96); k-quarter
//   kq=tid/96 -> k in [16kq,16kq+16), e in [8kq, 8kq+8) (kq=3: e=24 only).
//   Shared h/x loads are reused across the 2 columns (halves LDS issue).
//   Partials in srec[4]/sxh[4]; gates (all 448 = row x j) sum 4 quarters.
// =====================================================================
__global__ __launch_bounds__(448, 1) void kB(const float* __restrict__ Uf,
                                             const float* __restrict__ bf,
                                             const float* __restrict__ Ub,
                                             const float* __restrict__ bb,
                                             const float* __restrict__ Wf,
                                             const float* __restrict__ Wb) {
    __shared__ __align__(16) float sh[BT][HH];
    __shared__ __align__(16) float srec[4][BT][G3];
    __shared__ __align__(16) float sxh[4][BT][HH];
    __shared__ __align__(16) float xbuf[2][BT][EMB_P];

    const int tid = threadIdx.x;
    const int dir = blockIdx.x / BLK_PER_DIR;
    const int tile = blockIdx.x - dir * BLK_PER_DIR;
    const int b0 = tile * BT;

    const float* U   = dir ? Ub : Uf;
    const float* W   = dir ? Wb : Wf;
    const float* bia = dir ? bb : bf;      // [2][192]: row0 input bias, row1 recurrent bias
    float* hs        = dir ? g_hsb : g_hsf;

    const bool mv = tid < 384;
    const int p  = tid % 96;               // col pair id
    const int kq = tid / 96;               // k quarter 0..3 (warp-aligned: 96=3 warps)
    const int c0 = p, c1 = p + 96;
    const int k0 = kq * 16;
    const int e0 = kq * 8;
    const bool ep = kq < 3;                // 8 e-values (else 1 tail value)
    const bool c1h = c1 >= 128;            // col1 is in the h-chunk

    unsigned long long u2a[8], u2b[8];     // U pairs for col0/col1
    unsigned long long wxa[4], wxb[4];     // W pairs for col0/col1 (kq<3)
    float wta = 0.0f, wtb = 0.0f;          // kq==3 tail weights
    unsigned long long hb2a = pack2(0.f, 0.f), hb2b = pack2(0.f, 0.f);
    unsigned long long xb2a = pack2(0.f, 0.f), xb2b = pack2(0.f, 0.f);
    if (mv) {
#pragma unroll
        for (int t = 0; t < 8; t++) {
            u2a[t] = pack2(U[(k0 + 2 * t) * G3 + c0], U[(k0 + 2 * t + 1) * G3 + c0]);
            u2b[t] = pack2(U[(k0 + 2 * t) * G3 + c1], U[(k0 + 2 * t + 1) * G3 + c1]);
        }
        if (ep) {
#pragma unroll
            for (int t = 0; t < 4; t++) {
                wxa[t] = pack2(W[(e0 + 2 * t) * G3 + c0], W[(e0 + 2 * t + 1) * G3 + c0]);
                wxb[t] = pack2(W[(e0 + 2 * t) * G3 + c1], W[(e0 + 2 * t + 1) * G3 + c1]);
            }
        } else {
            wta = W[24 * G3 + c0];
            wtb = W[24 * G3 + c1];
        }
        if (kq == 0) {
            hb2a = pack2(bia[G3 + c0], 0.f);  hb2b = pack2(bia[G3 + c1], 0.f);
            xb2a = pack2(bia[c0], 0.f);       xb2b = pack2(bia[c1], 0.f);
        }
    }

    const int gr = tid / HH, j = tid % HH;  // gate role (all 448 threads)
    const int bb_ = b0 + gr;
    const bool gv = bb_ < BATCH;

    sh[gr][j] = 0.0f;                       // all 7 rows zeroed (matvec reads them)

    // prologue: stage x for the first step
    {
        const int s0 = dir ? (SEQ - 1) : 0;
        if (tid < BT * EMB) {
            int r = tid / EMB, e = tid - r * EMB;
            xbuf[0][r][e] = (b0 + r < BATCH)
                ? g_x[((size_t)s0 * BATCH + (b0 + r)) * EMB + e] : 0.0f;
        }
    }
    __syncthreads();

    for (int si = 0; si < SEQ; si++) {
        const int s = dir ? (SEQ - 1 - si) : si;
        const int cur = si & 1, nxt = cur ^ 1;

        // prefetch next step's x (L2-resident) + this step's mask
        float xpre = 0.0f; int pr = 0, pe = 0; bool pv = false;
        if (tid < BT * EMB && si + 1 < SEQ) {
            pr = tid / EMB; pe = tid - pr * EMB;
            const int sn = dir ? (s - 1) : (s + 1);
            if (b0 + pr < BATCH)
                xpre = g_x[((size_t)sn * BATCH + (b0 + pr)) * EMB + pe];
            pv = true;
        }
        float m = 0.0f;
        if (gv) m = g_mask[s * BATCH + bb_];

        if (mv) {
#pragma unroll
            for (int r = 0; r < BT; r++) {
                const ulonglong2* hp = (const ulonglong2*)(&sh[r][k0]);
                unsigned long long ha = hb2a, hb = hb2b;
#pragma unroll
                for (int t = 0; t < 4; t++) {
                    ulonglong2 hv = hp[t];
                    ha = fma2(hv.x, u2a[2 * t],     ha);
                    hb = fma2(hv.x, u2b[2 * t],     hb);
                    ha = fma2(hv.y, u2a[2 * t + 1], ha);
                    hb = fma2(hv.y, u2b[2 * t + 1], hb);
                }
                unsigned long long xa = xb2a, xb = xb2b;
                float xs0, xs1;
                if (ep) {
                    const ulonglong2* xp = (const ulonglong2*)(&xbuf[cur][r][e0]);
                    ulonglong2 xv0 = xp[0], xv1 = xp[1];
                    xa = fma2(xv0.x, wxa[0], xa);  xb = fma2(xv0.x, wxb[0], xb);
                    xa = fma2(xv0.y, wxa[1], xa);  xb = fma2(xv0.y, wxb[1], xb);
                    xa = fma2(xv1.x, wxa[2], xa);  xb = fma2(xv1.x, wxb[2], xb);
                    xa = fma2(xv1.y, wxa[3], xa);  xb = fma2(xv1.y, wxb[3], xb);
                    xs0 = hsum2(xa); xs1 = hsum2(xb);
                } else {
                    float xt = xbuf[cur][r][24];
                    xs0 = fmaf(xt, wta, hsum2(xa));
                    xs1 = fmaf(xt, wtb, hsum2(xb));
                }
                float hs0 = hsum2(ha), hs1 = hsum2(hb);

                srec[kq][r][c0] = hs0 + xs0;       // c0 < 96: z/r chunk, additive
                if (c1h) {                          // h chunk: keep parts separate
                    srec[kq][r][c1] = hs1;
                    sxh[kq][r][c1 - 128] = xs1;
                } else {
                    srec[kq][r][c1] = hs1 + xs1;
                }
            }
        }
        if (pv) xbuf[nxt][pr][pe] = xpre;
        __syncthreads();

        if (gv) {
            float az = srec[0][gr][j] + srec[1][gr][j]
                     + srec[2][gr][j] + srec[3][gr][j];
            float ar = srec[0][gr][HH + j] + srec[1][gr][HH + j]
                     + srec[2][gr][HH + j] + srec[3][gr][HH + j];
            float rh = srec[0][gr][2 * HH + j] + srec[1][gr][2 * HH + j]
                     + srec[2][gr][2 * HH + j] + srec[3][gr][2 * HH + j];
            float xh = sxh[0][gr][j] + sxh[1][gr][j]
                     + sxh[2][gr][j] + sxh[3][gr][j];
            float z   = sigx(az);
            float rg  = sigx(ar);
            float hhv = tanhx(xh + rg * rh);
            float hold = sh[gr][j];
            float hn = z * hold + (1.0f - z) * hhv;
            hn = hold + m * (hn - hold);            // masked update
            sh[gr][j] = hn;
            hs[((size_t)s * BATCH + bb_) * HH + j] = hn;
        }
        __syncthreads();
    }

    if (dir == 0 && gv) g_hT[bb_ * HH + j] = sh[gr][j];
}

// =====================================================================
// Kernel C: attention. grid = 512 (one block per batch), 256 threads.
//   Chunked over 8 timesteps; next chunk's rows prefetched into registers
//   (1 LDG.128/thread) while the current chunk computes.
// =====================================================================
__global__ __launch_bounds__(256) void kC(const float* __restrict__ Wk,
                                          const float* __restrict__ bk,
                                          const float* __restrict__ Wq,
                                          const float* __restrict__ bq,
                                          const float* __restrict__ We,
                                          const float* __restrict__ be,
                                          float* __restrict__ out) {
    __shared__ __align__(16) float sout[8][2 * HH];   // 8 timesteps of concat out
    __shared__ float spp[8][2][HH];                   // partial keys per k-half
    __shared__ float sq[HH], sbk[HH], sWe[HH];
    __shared__ float se[SEQ];
    __shared__ float sinv;

    const int tid = threadIdx.x;
    const int b = blockIdx.x;

    const int sl = tid / 128;            // 0/1 : handles s_local [sl*4, sl*4+4)
    const int inner = tid & 127;
    const int kh = inner / HH;           // 0/1 : k in [kh*64, kh*64+64)
    const int j = inner & (HH - 1);

    // staging role: thread loads one float4 of the chunk
    const int st_row = tid >> 5;                  // 0..7 (s within chunk)
    const int st_k   = (tid & 31) * 4;            // 0..124
    const float* st_base = (st_k < HH)
        ? (g_hsf + (size_t)b * HH + st_k)
        : (g_hsb + (size_t)b * HH + (st_k - HH));

    unsigned long long w2[32];           // (W_k[k][j], W_k[k+1][j]) for my half
#pragma unroll
    for (int t = 0; t < 32; t++)
        w2[t] = pack2(Wk[(kh * HH + 2 * t) * HH + j], Wk[(kh * HH + 2 * t + 1) * HH + j]);

    if (tid < HH) {
        float q = bq[tid];
#pragma unroll
        for (int k = 0; k < HH; k++) q += g_hT[b * HH + k] * Wq[k * HH + tid];
        sq[tid] = q;
        sbk[tid] = bk[tid];
        sWe[tid] = We[tid];
    }

    const float be0 = be[0];

    // prefetch chunk 0
    float4 v = *(const float4*)(st_base + (size_t)st_row * (BATCH * HH));
    __syncthreads();

    for (int ch = 0; ch < SEQ / 8; ch++) {
        const int s0 = ch * 8;
        *(float4*)&sout[st_row][st_k] = v;
        __syncthreads();

        if (ch + 1 < SEQ / 8)
            v = *(const float4*)(st_base + (size_t)(s0 + 8 + st_row) * (BATCH * HH));

        float pacc[4];
#pragma unroll
        for (int ss = 0; ss < 4; ss++) {
            const ulonglong2* op = (const ulonglong2*)(&sout[sl * 4 + ss][kh * HH]);
            unsigned long long a0 = pack2(0.0f, 0.0f), a1 = pack2(0.0f, 0.0f);
#pragma unroll
            for (int t = 0; t < 16; t++) {
                ulonglong2 ov = op[t];
                a0 = fma2(ov.x, w2[2 * t],     a0);
                a1 = fma2(ov.y, w2[2 * t + 1], a1);
            }
            pacc[ss] = hsum2(a0) + hsum2(a1);
        }
#pragma unroll
        for (int ss = 0; ss < 4; ss++) spp[sl * 4 + ss][kh][j] = pacc[ss];
        __syncthreads();

        {
            const int sidx = tid / 32, lane = tid & 31;
            float acc = 0.0f;
#pragma unroll
            for (int h = 0; h < 2; h++) {
                int jj = lane + h * 32;
                float key = spp[sidx][0][jj] + spp[sidx][1][jj] + sbk[jj];
                acc += tanhx(key + sq[jj]) * sWe[jj];
            }
#pragma unroll
            for (int off = 16; off > 0; off >>= 1)
                acc += __shfl_xor_sync(0xFFFFFFFFu, acc, off);
            if (lane == 0) {
                int s = s0 + sidx;
                float msk = g_mask[s * BATCH + b];
                se[s] = acc + be0 + (1.0f - msk) * (-1e9f);
            }
        }
        __syncthreads();
    }

    if (tid < 32) {
        float mx = -1e30f;
        for (int s = tid; s < SEQ; s += 32) mx = fmaxf(mx, se[s]);
#pragma unroll
        for (int off = 16; off > 0; off >>= 1)
            mx = fmaxf(mx, __shfl_xor_sync(0xFFFFFFFFu, mx, off));
        float sum = 0.0f;
        for (int s = tid; s < SEQ; s += 32) {
            float pz = __expf(se[s] - mx);
            se[s] = pz; sum += pz;
        }
#pragma unroll
        for (int off = 16; off > 0; off >>= 1)
            sum += __shfl_xor_sync(0xFFFFFFFFu, sum, off);
        if (tid == 0) sinv = __fdividef(1.0f, sum);
    }
    __syncthreads();

    if (tid < 2 * HH) {
        const int k = tid;
        const float* src = (k < HH) ? (g_hsf + (size_t)b * HH + k)
                                    : (g_hsb + (size_t)b * HH + (k - HH));
        float ctx = 0.0f;
#pragma unroll 4
        for (int s = 0; s < SEQ; s++)
            ctx += se[s] * src[(size_t)s * (BATCH * HH)];
        out[b * (2 * HH) + k] = ctx * sinv;
    }
}

// =====================================================================
extern "C" void kernel_launch(void* const* d_in, const int* in_sizes, int n_in,
                              void* d_out, int out_size) {
    const int*   inp = (const int*)d_in[0];
    const float* emb = (const float*)d_in[1];
    const float* Wf  = (const float*)d_in[2];
    const float* Uf  = (const float*)d_in[3];
    const float* bf  = (const float*)d_in[4];
    const float* Wb  = (const float*)d_in[5];
    const float* Ub  = (const float*)d_in[6];
    const float* bb  = (const float*)d_in[7];
    const float* Wk  = (const float*)d_in[8];
    const float* bk  = (const float*)d_in[9];
    const float* Wq  = (const float*)d_in[10];
    const float* bq  = (const float*)d_in[11];
    const float* We  = (const float*)d_in[12];
    const float* be  = (const float*)d_in[13];
    float* out = (float*)d_out;

    kD<<<1, 32>>>(0);                                  // launch-alignment dummies:
    kD<<<1, 32>>>(1);                                  // aim ncu's -s 5 -c 1 at kB
    kA<<<(BATCH * SEQ) / 32, 256>>>(inp, emb);
    kB<<<2 * BLK_PER_DIR, 448>>>(Uf, bf, Ub, bb, Wf, Wb);
    kC<<<BATCH, 256>>>(Wk, bk, Wq, bq, We, be, out);
}